// round 15
// baseline (speedup 1.0000x reference)
#include <cuda_runtime.h>
#include <cuda_bf16.h>
#include <cstdint>

#define B_      2
#define H_      16
#define L_      8192
#define D_      64
#define WIN     512
#define NW      16
#define FADE_   64
#define KC      64
#define NCH     (WIN / KC)   // 8
#define THREADS 128

// dynamic smem: two 32KB K/V buffers + persistent 32KB Q region = 96KB
#define BUF_KH  0
#define BUF_KL  8192
#define BUF_VH  16384
#define BUF_VL  24576
#define SM_QH   65536
#define SM_QL   81920
#define SM_TOT  98304

// Q pre-scale: 1/sqrt(64) * log2(e)  (turns exp into ex2)
#define QSCALE  (0.125f * 1.44269504088896340736f)

__device__ float g_cos[L_ * 32];
__device__ float g_sin[L_ * 32];

// ---------------- helpers ----------------
__device__ __forceinline__ uint32_t smem_u32(const void* p) {
    uint32_t a;
    asm("{ .reg .u64 t; cvta.to.shared.u64 t, %1; cvt.u32.u64 %0, t; }" : "=r"(a) : "l"(p));
    return a;
}
__device__ __forceinline__ uint32_t bf16x2_rn(float fo, float fe) {
    uint32_t w;
    asm("cvt.rn.bf16x2.f32 %0, %1, %2;" : "=r"(w) : "f"(fo), "f"(fe));
    return w;
}
__device__ __forceinline__ void split2(float fe, float fo, uint32_t& whi, uint32_t& wlo) {
    whi = bf16x2_rn(fo, fe);
    float fe_hi = __uint_as_float(whi << 16);
    float fo_hi = __uint_as_float(whi & 0xFFFF0000u);
    wlo = bf16x2_rn(fo - fo_hi, fe - fe_hi);
}
__device__ __forceinline__ float ex2(float x) {
    float d; asm("ex2.approx.f32 %0, %1;" : "=f"(d) : "f"(x)); return d;
}
__device__ __forceinline__ void sts128(uint32_t a, uint32_t x, uint32_t y, uint32_t z, uint32_t w) {
    asm volatile("st.shared.v4.b32 [%0], {%1,%2,%3,%4};" :: "r"(a), "r"(x), "r"(y), "r"(z), "r"(w));
}

#define LDSM_X4(r0, r1, r2, r3, a)                                            \
    asm volatile("ldmatrix.sync.aligned.m8n8.x4.shared.b16 {%0,%1,%2,%3}, [%4];" \
        : "=r"(r0), "=r"(r1), "=r"(r2), "=r"(r3) : "r"(a))
#define LDSM_X4T(r0, r1, r2, r3, a)                                           \
    asm volatile("ldmatrix.sync.aligned.m8n8.x4.trans.shared.b16 {%0,%1,%2,%3}, [%4];" \
        : "=r"(r0), "=r"(r1), "=r"(r2), "=r"(r3) : "r"(a))

#define MMA16816(c, a0, a1, a2, a3, b0, b1)                                   \
    asm volatile("mma.sync.aligned.m16n8k16.row.col.f32.bf16.bf16.f32 "       \
        "{%0,%1,%2,%3}, {%4,%5,%6,%7}, {%8,%9}, {%0,%1,%2,%3};"               \
        : "+f"((c)[0]), "+f"((c)[1]), "+f"((c)[2]), "+f"((c)[3])              \
        : "r"(a0), "r"(a1), "r"(a2), "r"(a3), "r"(b0), "r"(b1))

// ---- RoPE cos/sin table (dtype-probing position_ids) ----
__global__ void rope_table_kernel(const void* __restrict__ pos_raw) {
    int idx = blockIdx.x * blockDim.x + threadIdx.x;
    if (idx >= L_ * 32) return;
    int l = idx >> 5;
    int i = idx & 31;
    const int*       p32 = (const int*)pos_raw;
    const long long* p64 = (const long long*)pos_raw;
    bool is64 = (p32[1] == 0) && (p32[3] == 0);
    float posl = is64 ? (float)p64[l] : (float)p32[l];
    float e    = (float)(2 * i) / 64.0f;
    float invf = 1.0f / powf(10000.0f, e);
    float ang  = posl * invf;
    float s, c;
    sincosf(ang, &s, &c);
    g_cos[idx] = c;
    g_sin[idx] = s;
}

// ---- per-chunk staging (each thread: key jK, dim-half h2) ----
__device__ __forceinline__ void stage_K(const float* __restrict__ K, size_t bh,
                                        int lk0, uint32_t base, int jK, int h2) {
    const int lk = lk0 + jK;
    const float4* kp = (const float4*)(K + bh + (size_t)lk * D_);
    const float4* cp = (const float4*)(g_cos + (size_t)lk * 32);
    const float4* sp = (const float4*)(g_sin + (size_t)lk * 32);
    float lo[16], hi[16];
#pragma unroll
    for (int i = 0; i < 4; ++i) {
        float4 x1 = kp[h2 * 4 + i], x2 = kp[8 + h2 * 4 + i];
        float4 c = cp[h2 * 4 + i], s = sp[h2 * 4 + i];
        lo[4 * i + 0] = x1.x * c.x - x2.x * s.x;  hi[4 * i + 0] = x2.x * c.x + x1.x * s.x;
        lo[4 * i + 1] = x1.y * c.y - x2.y * s.y;  hi[4 * i + 1] = x2.y * c.y + x1.y * s.y;
        lo[4 * i + 2] = x1.z * c.z - x2.z * s.z;  hi[4 * i + 2] = x2.z * c.z + x1.z * s.z;
        lo[4 * i + 3] = x1.w * c.w - x2.w * s.w;  hi[4 * i + 3] = x2.w * c.w + x1.w * s.w;
    }
    const uint32_t rb = base + (uint32_t)(jK * 128);
    const uint32_t jx = (uint32_t)(jK & 7);
#pragma unroll
    for (int half = 0; half < 2; ++half) {
        const float* src = half ? hi : lo;
        int seg0 = half * 4 + 2 * h2;
#pragma unroll
        for (int ss = 0; ss < 2; ++ss) {
            uint32_t hr[4], lr[4];
#pragma unroll
            for (int k = 0; k < 4; ++k)
                split2(src[8 * ss + 2 * k], src[8 * ss + 2 * k + 1], hr[k], lr[k]);
            uint32_t off = (((uint32_t)(seg0 + ss) ^ jx) << 4);
            sts128(rb + BUF_KH + off, hr[0], hr[1], hr[2], hr[3]);
            sts128(rb + BUF_KL + off, lr[0], lr[1], lr[2], lr[3]);
        }
    }
}

__device__ __forceinline__ void stage_V(const float* __restrict__ V, size_t bh,
                                        int lk0, uint32_t base, int jK, int h2) {
    const float4* vp = (const float4*)(V + bh + (size_t)(lk0 + jK) * D_);
    const uint32_t rb = base + (uint32_t)(jK * 128);
    const uint32_t jx = (uint32_t)(jK & 7);
#pragma unroll
    for (int ss = 0; ss < 4; ++ss) {
        float4 xa = vp[h2 * 8 + 2 * ss];
        float4 xb = vp[h2 * 8 + 2 * ss + 1];
        uint32_t hr[4], lr[4];
        split2(xa.x, xa.y, hr[0], lr[0]);
        split2(xa.z, xa.w, hr[1], lr[1]);
        split2(xb.x, xb.y, hr[2], lr[2]);
        split2(xb.z, xb.w, hr[3], lr[3]);
        uint32_t off = (((uint32_t)(4 * h2 + ss) ^ jx) << 4);
        sts128(rb + BUF_VH + off, hr[0], hr[1], hr[2], hr[3]);
        sts128(rb + BUF_VL + off, lr[0], lr[1], lr[2], lr[3]);
    }
}

// ---------------- main HMMA attention kernel ----------------
__global__ void __launch_bounds__(THREADS, 2)
swa_mma_kernel(const float* __restrict__ Q, const float* __restrict__ K,
               const float* __restrict__ V, float* __restrict__ Out) {
    extern __shared__ __align__(16) uint8_t smem_raw[];
    const uint32_t smb = smem_u32(smem_raw);

    const int tid = threadIdx.x;
    const int w   = tid >> 5;
    const int l   = tid & 31;
    const int g   = l >> 2;
    const int tig = l & 3;
    const int b3  = (l >> 3) & 1;
    const int b4  = l >> 4;
    const int l7  = l & 7;

    const int n  = blockIdx.x >> 2;
    const int qt = blockIdx.x & 3;
    const int hh = blockIdx.y;
    const int b  = blockIdx.z;
    const size_t bh = (size_t)(b * H_ + hh) * L_ * D_;

    const int jK = tid >> 1;
    const int h2 = tid & 1;

    // ---- stage Q (row = tid): RoPE + QSCALE + split -> persistent smem ----
    {
        const int lq = n * WIN + qt * 128 + tid;
        float of[64];
        const float4* qp = (const float4*)(Q + bh + (size_t)lq * D_);
        const float4* cp = (const float4*)(g_cos + (size_t)lq * 32);
        const float4* sp = (const float4*)(g_sin + (size_t)lq * 32);
#pragma unroll
        for (int k = 0; k < 8; ++k) {
            float4 x1 = qp[k], x2 = qp[k + 8], c = cp[k], s = sp[k];
            of[4 * k + 0] = (x1.x * c.x - x2.x * s.x) * QSCALE;
            of[4 * k + 1] = (x1.y * c.y - x2.y * s.y) * QSCALE;
            of[4 * k + 2] = (x1.z * c.z - x2.z * s.z) * QSCALE;
            of[4 * k + 3] = (x1.w * c.w - x2.w * s.w) * QSCALE;
            of[32 + 4 * k + 0] = (x2.x * c.x + x1.x * s.x) * QSCALE;
            of[32 + 4 * k + 1] = (x2.y * c.y + x1.y * s.y) * QSCALE;
            of[32 + 4 * k + 2] = (x2.z * c.z + x1.z * s.z) * QSCALE;
            of[32 + 4 * k + 3] = (x2.w * c.w + x1.w * s.w) * QSCALE;
        }
#pragma unroll
        for (int s = 0; s < 8; ++s) {
            uint32_t hr[4], lr[4];
#pragma unroll
            for (int k = 0; k < 4; ++k)
                split2(of[8 * s + 2 * k], of[8 * s + 2 * k + 1], hr[k], lr[k]);
            uint32_t off = (uint32_t)(tid * 128 + ((s ^ (tid & 7)) << 4));
            sts128(smb + SM_QH + off, hr[0], hr[1], hr[2], hr[3]);
            sts128(smb + SM_QL + off, lr[0], lr[1], lr[2], lr[3]);
        }
    }

    // stage chunk 0 into buf0, then one sync covers Q + chunk 0
    stage_K(K, bh, n * WIN, smb, jK, h2);
    stage_V(V, bh, n * WIN, smb, jK, h2);
    __syncthreads();

    float o[64];
#pragma unroll
    for (int i = 0; i < 64; ++i) o[i] = 0.0f;
    float lsum[4] = {0.f, 0.f, 0.f, 0.f};

    const uint32_t qrow_base = (uint32_t)(w * 32 + b3 * 8 + l7);
    const uint32_t krow_base = (uint32_t)(b4 * 8 + l7);
    const uint32_t vrow_base = (uint32_t)(b3 * 8 + l7);

    for (int ch = 0; ch < NCH; ++ch) {
        const uint32_t bufc = smb + (uint32_t)((ch & 1) << 15);
        const uint32_t bufn = smb + (uint32_t)(((ch + 1) & 1) << 15);
        const int lk0n = n * WIN + (ch + 1) * KC;

        // prefetch next chunk's K under the QK MMA block
        if (ch < NCH - 1) stage_K(K, bh, lk0n, bufn, jK, h2);

        // ---- QK^T: S = Qhi*Khi + Qhi*Klo + Qlo*Khi ----
        float c[64];
#pragma unroll
        for (int i = 0; i < 64; ++i) c[i] = 0.0f;

#pragma unroll
        for (int kk = 0; kk < 4; ++kk) {
            uint32_t ah[2][4], al[2][4];
#pragma unroll
            for (int mt = 0; mt < 2; ++mt) {
                uint32_t qoff = (uint32_t)((qrow_base + mt * 16) * 128 +
                                           (((2 * kk + b4) ^ l7) << 4));
                LDSM_X4(ah[mt][0], ah[mt][1], ah[mt][2], ah[mt][3], smb + SM_QH + qoff);
                LDSM_X4(al[mt][0], al[mt][1], al[mt][2], al[mt][3], smb + SM_QL + qoff);
            }
#pragma unroll
            for (int ntp = 0; ntp < 4; ++ntp) {
                uint32_t koff = (uint32_t)((krow_base + ntp * 16) * 128 +
                                           (((2 * kk + b3) ^ l7) << 4));
                uint32_t kh0, kh1, kh2, kh3, kl0, kl1, kl2, kl3;
                LDSM_X4(kh0, kh1, kh2, kh3, bufc + BUF_KH + koff);
                LDSM_X4(kl0, kl1, kl2, kl3, bufc + BUF_KL + koff);
#pragma unroll
                for (int mt = 0; mt < 2; ++mt) {
                    float* c0 = &c[mt * 32 + (2 * ntp) * 4];
                    float* c1 = &c[mt * 32 + (2 * ntp + 1) * 4];
                    MMA16816(c0, ah[mt][0], ah[mt][1], ah[mt][2], ah[mt][3], kh0, kh1);
                    MMA16816(c1, ah[mt][0], ah[mt][1], ah[mt][2], ah[mt][3], kh2, kh3);
                    MMA16816(c0, ah[mt][0], ah[mt][1], ah[mt][2], ah[mt][3], kl0, kl1);
                    MMA16816(c1, ah[mt][0], ah[mt][1], ah[mt][2], ah[mt][3], kl2, kl3);
                    MMA16816(c0, al[mt][0], al[mt][1], al[mt][2], al[mt][3], kh0, kh1);
                    MMA16816(c1, al[mt][0], al[mt][1], al[mt][2], al[mt][3], kh2, kh3);
                }
            }
        }

        // ---- softmax numerator: p = 2^S; split -> PV A frags ----
        uint32_t ph[2][4][4], pl[2][4][4];
#pragma unroll
        for (int mt = 0; mt < 2; ++mt) {
#pragma unroll
            for (int kk = 0; kk < 4; ++kk) {
                float* c0 = &c[mt * 32 + (2 * kk) * 4];
                float* c1 = &c[mt * 32 + (2 * kk + 1) * 4];
                float p00 = ex2(c0[0]), p01 = ex2(c0[1]);
                float p02 = ex2(c0[2]), p03 = ex2(c0[3]);
                float p10 = ex2(c1[0]), p11 = ex2(c1[1]);
                float p12 = ex2(c1[2]), p13 = ex2(c1[3]);
                lsum[mt * 2 + 0] += (p00 + p01) + (p10 + p11);
                lsum[mt * 2 + 1] += (p02 + p03) + (p12 + p13);
                split2(p00, p01, ph[mt][kk][0], pl[mt][kk][0]);
                split2(p02, p03, ph[mt][kk][1], pl[mt][kk][1]);
                split2(p10, p11, ph[mt][kk][2], pl[mt][kk][2]);
                split2(p12, p13, ph[mt][kk][3], pl[mt][kk][3]);
            }
        }

        // prefetch next chunk's V under the PV MMA block
        if (ch < NCH - 1) stage_V(V, bh, lk0n, bufn, jK, h2);

        // ---- PV: O += Phi*Vhi + Phi*Vlo + Plo*Vhi ----
#pragma unroll
        for (int kk = 0; kk < 4; ++kk) {
#pragma unroll
            for (int ntp = 0; ntp < 4; ++ntp) {
                uint32_t voff = (uint32_t)((vrow_base + kk * 16) * 128 +
                                           (((2 * ntp + b4) ^ l7) << 4));
                uint32_t vh0, vh1, vh2, vh3, vl0, vl1, vl2, vl3;
                LDSM_X4T(vh0, vh1, vh2, vh3, bufc + BUF_VH + voff);
                LDSM_X4T(vl0, vl1, vl2, vl3, bufc + BUF_VL + voff);
#pragma unroll
                for (int mt = 0; mt < 2; ++mt) {
                    float* o0 = &o[mt * 32 + (2 * ntp) * 4];
                    float* o1 = &o[mt * 32 + (2 * ntp + 1) * 4];
                    MMA16816(o0, ph[mt][kk][0], ph[mt][kk][1], ph[mt][kk][2], ph[mt][kk][3], vh0, vh1);
                    MMA16816(o1, ph[mt][kk][0], ph[mt][kk][1], ph[mt][kk][2], ph[mt][kk][3], vh2, vh3);
                    MMA16816(o0, ph[mt][kk][0], ph[mt][kk][1], ph[mt][kk][2], ph[mt][kk][3], vl0, vl1);
                    MMA16816(o1, ph[mt][kk][0], ph[mt][kk][1], ph[mt][kk][2], ph[mt][kk][3], vl2, vl3);
                    MMA16816(o0, pl[mt][kk][0], pl[mt][kk][1], pl[mt][kk][2], pl[mt][kk][3], vh0, vh1);
                    MMA16816(o1, pl[mt][kk][0], pl[mt][kk][1], pl[mt][kk][2], pl[mt][kk][3], vh2, vh3);
                }
            }
        }

        if (ch < NCH - 1) __syncthreads();
    }

    // ---- row-sum reduce across the 4 lanes sharing a row ----
#pragma unroll
    for (int i = 0; i < 4; ++i) {
        lsum[i] += __shfl_xor_sync(0xffffffffu, lsum[i], 1);
        lsum[i] += __shfl_xor_sync(0xffffffffu, lsum[i], 2);
    }

    // ---- epilogue: fade weight, normalize, store ----
#pragma unroll
    for (int mt = 0; mt < 2; ++mt) {
#pragma unroll
        for (int rh = 0; rh < 2; ++rh) {
            int r  = qt * 128 + w * 32 + mt * 16 + rh * 8 + g;
            int lq = n * WIN + r;
            float wgt = 1.0f;
            if (n != 0 && n != NW - 1) {
                if (r < FADE_)              wgt = (float)r * (1.0f / 63.0f);
                else if (r >= WIN - FADE_)  wgt = (float)(WIN - 1 - r) * (1.0f / 63.0f);
            }
            float sc = (wgt / (wgt + 1e-8f)) / lsum[mt * 2 + rh];
            float* dst = (float*)(Out + bh + (size_t)lq * D_);
#pragma unroll
            for (int nt = 0; nt < 8; ++nt) {
                float2 v;
                v.x = o[mt * 32 + nt * 4 + rh * 2 + 0] * sc;
                v.y = o[mt * 32 + nt * 4 + rh * 2 + 1] * sc;
                *(float2*)(dst + nt * 8 + tig * 2) = v;
            }
        }
    }
}

extern "C" void kernel_launch(void* const* d_in, const int* in_sizes, int n_in,
                              void* d_out, int out_size) {
    const float* Q   = (const float*)d_in[0];
    const float* K   = (const float*)d_in[1];
    const float* V   = (const float*)d_in[2];
    const void*  pos = (const void*)d_in[3];
    float* Out = (float*)d_out;

    cudaFuncSetAttribute(swa_mma_kernel,
                         cudaFuncAttributeMaxDynamicSharedMemorySize, SM_TOT);

    rope_table_kernel<<<(L_ * 32 + 255) / 256, 256>>>(pos);

    dim3 grid(NW * 4, H_, B_);
    swa_mma_kernel<<<grid, THREADS, SM_TOT>>>(Q, K, V, Out);
}

// round 17
// speedup vs baseline: 1.3617x; 1.3617x over previous
#include <cuda_runtime.h>
#include <cuda_bf16.h>
#include <cuda_fp16.h>
#include <cstdint>

#define B_      2
#define H_      16
#define L_      8192
#define D_      64
#define WIN     512
#define NW      16
#define FADE_   64
#define KC      64
#define NCH     (WIN / KC)   // 8
#define THREADS 128
#define NCHUNK  (L_ / KC)    // 128 chunks per (b,h)

// smem: two 24KB K/V buffers (KH,KL,VH) + persistent 32KB Q = 80KB
#define BUF_KH  0
#define BUF_KL  8192
#define BUF_VH  16384
#define BUF_SZ  24576
#define SM_QH   49152
#define SM_QL   65536
#define SM_TOT  81920

// Q pre-scale: 1/sqrt(64) * log2(e)  (turns exp into ex2)
#define QSCALE  (0.125f * 1.44269504088896340736f)

__device__ float g_cos[L_ * 32];
__device__ float g_sin[L_ * 32];
// Pre-transformed tiles, 8KB per (bh,chunk), exact smem image (swizzle baked in)
__device__ __align__(16) uint8_t g_KH[(size_t)32 * NCHUNK * 8192];  // bf16 K hi
__device__ __align__(16) uint8_t g_KL[(size_t)32 * NCHUNK * 8192];  // bf16 K lo
__device__ __align__(16) uint8_t g_VH[(size_t)32 * NCHUNK * 8192];  // fp16 V

// ---------------- helpers ----------------
__device__ __forceinline__ uint32_t smem_u32(const void* p) {
    uint32_t a;
    asm("{ .reg .u64 t; cvta.to.shared.u64 t, %1; cvt.u32.u64 %0, t; }" : "=r"(a) : "l"(p));
    return a;
}
__device__ __forceinline__ uint32_t bf16x2_rn(float fo, float fe) {
    uint32_t w;
    asm("cvt.rn.bf16x2.f32 %0, %1, %2;" : "=r"(w) : "f"(fo), "f"(fe));
    return w;
}
__device__ __forceinline__ void split2(float fe, float fo, uint32_t& whi, uint32_t& wlo) {
    whi = bf16x2_rn(fo, fe);
    float fe_hi = __uint_as_float(whi << 16);
    float fo_hi = __uint_as_float(whi & 0xFFFF0000u);
    wlo = bf16x2_rn(fo - fo_hi, fe - fe_hi);
}
__device__ __forceinline__ uint32_t packh2(float fe, float fo) {
    __half2 h = __floats2half2_rn(fe, fo);
    return *reinterpret_cast<uint32_t*>(&h);
}
__device__ __forceinline__ void split2h(float fe, float fo, uint32_t& whi, uint32_t& wlo) {
    __half2 h = __floats2half2_rn(fe, fo);
    float2 hf = __half22float2(h);
    __half2 lr = __floats2half2_rn(fe - hf.x, fo - hf.y);
    whi = *reinterpret_cast<uint32_t*>(&h);
    wlo = *reinterpret_cast<uint32_t*>(&lr);
}
__device__ __forceinline__ float ex2(float x) {
    float d; asm("ex2.approx.f32 %0, %1;" : "=f"(d) : "f"(x)); return d;
}
__device__ __forceinline__ void sts128(uint32_t a, uint32_t x, uint32_t y, uint32_t z, uint32_t w) {
    asm volatile("st.shared.v4.b32 [%0], {%1,%2,%3,%4};" :: "r"(a), "r"(x), "r"(y), "r"(z), "r"(w));
}
__device__ __forceinline__ void cpa16(uint32_t s, const void* g) {
    asm volatile("cp.async.cg.shared.global [%0], [%1], 16;" :: "r"(s), "l"(g));
}
#define CP_COMMIT() asm volatile("cp.async.commit_group;" ::: "memory")
#define CP_WAIT(n)  asm volatile("cp.async.wait_group %0;" :: "n"(n) : "memory")

#define LDSM_X4(r0, r1, r2, r3, a)                                            \
    asm volatile("ldmatrix.sync.aligned.m8n8.x4.shared.b16 {%0,%1,%2,%3}, [%4];" \
        : "=r"(r0), "=r"(r1), "=r"(r2), "=r"(r3) : "r"(a))
#define LDSM_X4T(r0, r1, r2, r3, a)                                           \
    asm volatile("ldmatrix.sync.aligned.m8n8.x4.trans.shared.b16 {%0,%1,%2,%3}, [%4];" \
        : "=r"(r0), "=r"(r1), "=r"(r2), "=r"(r3) : "r"(a))

#define MMA16816(c, a0, a1, a2, a3, b0, b1)                                   \
    asm volatile("mma.sync.aligned.m16n8k16.row.col.f32.bf16.bf16.f32 "       \
        "{%0,%1,%2,%3}, {%4,%5,%6,%7}, {%8,%9}, {%0,%1,%2,%3};"               \
        : "+f"((c)[0]), "+f"((c)[1]), "+f"((c)[2]), "+f"((c)[3])              \
        : "r"(a0), "r"(a1), "r"(a2), "r"(a3), "r"(b0), "r"(b1))

#define MMA16816H(c, a0, a1, a2, a3, b0, b1)                                  \
    asm volatile("mma.sync.aligned.m16n8k16.row.col.f32.f16.f16.f32 "         \
        "{%0,%1,%2,%3}, {%4,%5,%6,%7}, {%8,%9}, {%0,%1,%2,%3};"               \
        : "+f"((c)[0]), "+f"((c)[1]), "+f"((c)[2]), "+f"((c)[3])              \
        : "r"(a0), "r"(a1), "r"(a2), "r"(a3), "r"(b0), "r"(b1))

// ---- RoPE cos/sin table (dtype-probing position_ids) ----
__global__ void rope_table_kernel(const void* __restrict__ pos_raw) {
    int idx = blockIdx.x * blockDim.x + threadIdx.x;
    if (idx >= L_ * 32) return;
    int l = idx >> 5;
    int i = idx & 31;
    const int*       p32 = (const int*)pos_raw;
    const long long* p64 = (const long long*)pos_raw;
    bool is64 = (p32[1] == 0) && (p32[3] == 0);
    float posl = is64 ? (float)p64[l] : (float)p32[l];
    float e    = (float)(2 * i) / 64.0f;
    float invf = 1.0f / powf(10000.0f, e);
    float ang  = posl * invf;
    float s, c;
    sincosf(ang, &s, &c);
    g_cos[idx] = c;
    g_sin[idx] = s;
}

// ---- pre-transform K (RoPE + bf16 split) and V (fp16) into tile images ----
__global__ void __launch_bounds__(128) prep_kv_kernel(const float* __restrict__ K,
                                                      const float* __restrict__ V) {
    const int blk  = blockIdx.x;          // bhid * NCHUNK + chunk
    const int tid  = threadIdx.x;
    const int jK   = tid >> 1;
    const int h2   = tid & 1;
    const int bhid = blk >> 7;
    const size_t base = (size_t)bhid * L_ * D_;
    const int lk = (blk & 127) * KC + jK;

    uint8_t* KHt = g_KH + (size_t)blk * 8192 + (uint32_t)(jK * 128);
    uint8_t* KLt = g_KL + (size_t)blk * 8192 + (uint32_t)(jK * 128);
    uint8_t* VHt = g_VH + (size_t)blk * 8192 + (uint32_t)(jK * 128);
    const uint32_t jx = (uint32_t)(jK & 7);

    // K: RoPE + split (d1 = dims 0..31 rotated, d2 = dims 32..63 rotated)
    {
        const float4* kp = (const float4*)(K + base + (size_t)lk * D_);
        const float4* cp = (const float4*)(g_cos + (size_t)lk * 32);
        const float4* sp = (const float4*)(g_sin + (size_t)lk * 32);
        float d1[16], d2[16];
#pragma unroll
        for (int i = 0; i < 4; ++i) {
            float4 x1 = kp[h2 * 4 + i], x2 = kp[8 + h2 * 4 + i];
            float4 c = cp[h2 * 4 + i], s = sp[h2 * 4 + i];
            d1[4 * i + 0] = x1.x * c.x - x2.x * s.x;  d2[4 * i + 0] = x2.x * c.x + x1.x * s.x;
            d1[4 * i + 1] = x1.y * c.y - x2.y * s.y;  d2[4 * i + 1] = x2.y * c.y + x1.y * s.y;
            d1[4 * i + 2] = x1.z * c.z - x2.z * s.z;  d2[4 * i + 2] = x2.z * c.z + x1.z * s.z;
            d1[4 * i + 3] = x1.w * c.w - x2.w * s.w;  d2[4 * i + 3] = x2.w * c.w + x1.w * s.w;
        }
#pragma unroll
        for (int half = 0; half < 2; ++half) {
            const float* src = half ? d2 : d1;
            int seg0 = half * 4 + 2 * h2;
#pragma unroll
            for (int ss = 0; ss < 2; ++ss) {
                uint32_t hr[4], lr[4];
#pragma unroll
                for (int k = 0; k < 4; ++k)
                    split2(src[8 * ss + 2 * k], src[8 * ss + 2 * k + 1], hr[k], lr[k]);
                uint32_t off = (((uint32_t)(seg0 + ss) ^ jx) << 4);
                *(uint4*)(KHt + off) = make_uint4(hr[0], hr[1], hr[2], hr[3]);
                *(uint4*)(KLt + off) = make_uint4(lr[0], lr[1], lr[2], lr[3]);
            }
        }
    }
    // V: fp16 convert, same tile layout
    {
        const float4* vp = (const float4*)(V + base + (size_t)lk * D_);
#pragma unroll
        for (int ss = 0; ss < 4; ++ss) {
            float4 xa = vp[h2 * 8 + 2 * ss];
            float4 xb = vp[h2 * 8 + 2 * ss + 1];
            uint32_t r0 = packh2(xa.x, xa.y);
            uint32_t r1 = packh2(xa.z, xa.w);
            uint32_t r2 = packh2(xb.x, xb.y);
            uint32_t r3 = packh2(xb.z, xb.w);
            uint32_t off = (((uint32_t)(4 * h2 + ss) ^ jx) << 4);
            *(uint4*)(VHt + off) = make_uint4(r0, r1, r2, r3);
        }
    }
}

// ---- async tile fetch: 24KB (KH,KL,VH) per chunk, 12 cp.async per thread ----
__device__ __forceinline__ void issue_chunk(uint32_t buf, int gchunk, int tid) {
    size_t off = (size_t)gchunk * 8192 + (uint32_t)(tid * 16);
    const uint8_t* kh = g_KH + off;
    const uint8_t* kl = g_KL + off;
    const uint8_t* vh = g_VH + off;
    uint32_t s = buf + (uint32_t)(tid * 16);
#pragma unroll
    for (int i = 0; i < 4; ++i) {
        cpa16(s + BUF_KH + i * 2048, kh + i * 2048);
        cpa16(s + BUF_KL + i * 2048, kl + i * 2048);
        cpa16(s + BUF_VH + i * 2048, vh + i * 2048);
    }
    CP_COMMIT();
}

// ---------------- main HMMA attention kernel ----------------
__global__ void __launch_bounds__(THREADS, 2)
swa_mma_kernel(const float* __restrict__ Q, float* __restrict__ Out) {
    extern __shared__ __align__(16) uint8_t smem_raw[];
    const uint32_t smb = smem_u32(smem_raw);

    const int tid = threadIdx.x;
    const int w   = tid >> 5;
    const int l   = tid & 31;
    const int g   = l >> 2;
    const int tig = l & 3;
    const int b3  = (l >> 3) & 1;
    const int b4  = l >> 4;
    const int l7  = l & 7;

    const int n  = blockIdx.x >> 2;
    const int qt = blockIdx.x & 3;
    const int hh = blockIdx.y;
    const int b  = blockIdx.z;
    const int bhid = b * H_ + hh;
    const size_t bho = (size_t)bhid * L_ * D_;
    const int gcb = bhid * NCHUNK + n * NCH;   // global chunk base for this window

    // kick off chunk 0 fetch immediately (overlaps Q staging below)
    issue_chunk(smb, gcb, tid);

    // ---- stage Q (row = tid): RoPE + QSCALE + split -> persistent smem ----
    {
        const int lq = n * WIN + qt * 128 + tid;
        float of[64];
        const float4* qp = (const float4*)(Q + bho + (size_t)lq * D_);
        const float4* cp = (const float4*)(g_cos + (size_t)lq * 32);
        const float4* sp = (const float4*)(g_sin + (size_t)lq * 32);
#pragma unroll
        for (int k = 0; k < 8; ++k) {
            float4 x1 = qp[k], x2 = qp[k + 8], c = cp[k], s = sp[k];
            of[4 * k + 0] = (x1.x * c.x - x2.x * s.x) * QSCALE;
            of[4 * k + 1] = (x1.y * c.y - x2.y * s.y) * QSCALE;
            of[4 * k + 2] = (x1.z * c.z - x2.z * s.z) * QSCALE;
            of[4 * k + 3] = (x1.w * c.w - x2.w * s.w) * QSCALE;
            of[32 + 4 * k + 0] = (x2.x * c.x + x1.x * s.x) * QSCALE;
            of[32 + 4 * k + 1] = (x2.y * c.y + x1.y * s.y) * QSCALE;
            of[32 + 4 * k + 2] = (x2.z * c.z + x1.z * s.z) * QSCALE;
            of[32 + 4 * k + 3] = (x2.w * c.w + x1.w * s.w) * QSCALE;
        }
#pragma unroll
        for (int s = 0; s < 8; ++s) {
            uint32_t hr[4], lr[4];
#pragma unroll
            for (int k = 0; k < 4; ++k)
                split2(of[8 * s + 2 * k], of[8 * s + 2 * k + 1], hr[k], lr[k]);
            uint32_t off = (uint32_t)(tid * 128 + ((s ^ (tid & 7)) << 4));
            sts128(smb + SM_QH + off, hr[0], hr[1], hr[2], hr[3]);
            sts128(smb + SM_QL + off, lr[0], lr[1], lr[2], lr[3]);
        }
    }

    float o[64];
#pragma unroll
    for (int i = 0; i < 64; ++i) o[i] = 0.0f;
    float lsum[4] = {0.f, 0.f, 0.f, 0.f};

    const uint32_t qrow_base = (uint32_t)(w * 32 + b3 * 8 + l7);
    const uint32_t krow_base = (uint32_t)(b4 * 8 + l7);
    const uint32_t vrow_base = (uint32_t)(b3 * 8 + l7);

    for (int ch = 0; ch < NCH; ++ch) {
        const uint32_t bufc = smb + (uint32_t)((ch & 1) ? BUF_SZ : 0);
        const uint32_t bufn = smb + (uint32_t)((ch & 1) ? 0 : BUF_SZ);

        if (ch < NCH - 1) {
            issue_chunk(bufn, gcb + ch + 1, tid);   // async prefetch, no reg chain
            CP_WAIT(1);                              // chunk ch landed
        } else {
            CP_WAIT(0);
        }
        __syncthreads();   // all threads' copies (and Q on first iter) visible

        // ---- QK^T: S = Qhi*Khi + Qhi*Klo + Qlo*Khi (bf16 3-chain) ----
        float c[64];
#pragma unroll
        for (int i = 0; i < 64; ++i) c[i] = 0.0f;

#pragma unroll
        for (int kk = 0; kk < 4; ++kk) {
            uint32_t ah[2][4], al[2][4];
#pragma unroll
            for (int mt = 0; mt < 2; ++mt) {
                uint32_t qoff = (uint32_t)((qrow_base + mt * 16) * 128 +
                                           (((2 * kk + b4) ^ l7) << 4));
                LDSM_X4(ah[mt][0], ah[mt][1], ah[mt][2], ah[mt][3], smb + SM_QH + qoff);
                LDSM_X4(al[mt][0], al[mt][1], al[mt][2], al[mt][3], smb + SM_QL + qoff);
            }
#pragma unroll
            for (int ntp = 0; ntp < 4; ++ntp) {
                uint32_t koff = (uint32_t)((krow_base + ntp * 16) * 128 +
                                           (((2 * kk + b3) ^ l7) << 4));
                uint32_t kh0, kh1, kh2, kh3, kl0, kl1, kl2, kl3;
                LDSM_X4(kh0, kh1, kh2, kh3, bufc + BUF_KH + koff);
                LDSM_X4(kl0, kl1, kl2, kl3, bufc + BUF_KL + koff);
#pragma unroll
                for (int mt = 0; mt < 2; ++mt) {
                    float* c0 = &c[mt * 32 + (2 * ntp) * 4];
                    float* c1 = &c[mt * 32 + (2 * ntp + 1) * 4];
                    MMA16816(c0, ah[mt][0], ah[mt][1], ah[mt][2], ah[mt][3], kh0, kh1);
                    MMA16816(c1, ah[mt][0], ah[mt][1], ah[mt][2], ah[mt][3], kh2, kh3);
                    MMA16816(c0, ah[mt][0], ah[mt][1], ah[mt][2], ah[mt][3], kl0, kl1);
                    MMA16816(c1, ah[mt][0], ah[mt][1], ah[mt][2], ah[mt][3], kl2, kl3);
                    MMA16816(c0, al[mt][0], al[mt][1], al[mt][2], al[mt][3], kh0, kh1);
                    MMA16816(c1, al[mt][0], al[mt][1], al[mt][2], al[mt][3], kh2, kh3);
                }
            }
        }

        // ---- softmax numerator: p = 2^S; fp16 split -> PV A frags ----
        uint32_t ph[2][4][4], pl[2][4][4];
#pragma unroll
        for (int mt = 0; mt < 2; ++mt) {
#pragma unroll
            for (int kk = 0; kk < 4; ++kk) {
                float* c0 = &c[mt * 32 + (2 * kk) * 4];
                float* c1 = &c[mt * 32 + (2 * kk + 1) * 4];
                float p00 = ex2(c0[0]), p01 = ex2(c0[1]);
                float p02 = ex2(c0[2]), p03 = ex2(c0[3]);
                float p10 = ex2(c1[0]), p11 = ex2(c1[1]);
                float p12 = ex2(c1[2]), p13 = ex2(c1[3]);
                lsum[mt * 2 + 0] += (p00 + p01) + (p10 + p11);
                lsum[mt * 2 + 1] += (p02 + p03) + (p12 + p13);
                split2h(p00, p01, ph[mt][kk][0], pl[mt][kk][0]);
                split2h(p02, p03, ph[mt][kk][1], pl[mt][kk][1]);
                split2h(p10, p11, ph[mt][kk][2], pl[mt][kk][2]);
                split2h(p12, p13, ph[mt][kk][3], pl[mt][kk][3]);
            }
        }

        // ---- PV: O += (Phi + Plo) * Vh (fp16 2-chain, V residual dropped) ----
#pragma unroll
        for (int kk = 0; kk < 4; ++kk) {
#pragma unroll
            for (int ntp = 0; ntp < 4; ++ntp) {
                uint32_t voff = (uint32_t)((vrow_base + kk * 16) * 128 +
                                           (((2 * ntp + b4) ^ l7) << 4));
                uint32_t vh0, vh1, vh2, vh3;
                LDSM_X4T(vh0, vh1, vh2, vh3, bufc + BUF_VH + voff);
#pragma unroll
                for (int mt = 0; mt < 2; ++mt) {
                    float* o0 = &o[mt * 32 + (2 * ntp) * 4];
                    float* o1 = &o[mt * 32 + (2 * ntp + 1) * 4];
                    MMA16816H(o0, ph[mt][kk][0], ph[mt][kk][1], ph[mt][kk][2], ph[mt][kk][3], vh0, vh1);
                    MMA16816H(o1, ph[mt][kk][0], ph[mt][kk][1], ph[mt][kk][2], ph[mt][kk][3], vh2, vh3);
                    MMA16816H(o0, pl[mt][kk][0], pl[mt][kk][1], pl[mt][kk][2], pl[mt][kk][3], vh0, vh1);
                    MMA16816H(o1, pl[mt][kk][0], pl[mt][kk][1], pl[mt][kk][2], pl[mt][kk][3], vh2, vh3);
                }
            }
        }

        if (ch < NCH - 1) __syncthreads();   // compute done before next overwrite
    }

    // ---- row-sum reduce across the 4 lanes sharing a row ----
#pragma unroll
    for (int i = 0; i < 4; ++i) {
        lsum[i] += __shfl_xor_sync(0xffffffffu, lsum[i], 1);
        lsum[i] += __shfl_xor_sync(0xffffffffu, lsum[i], 2);
    }

    // ---- epilogue: fade weight, normalize, store ----
#pragma unroll
    for (int mt = 0; mt < 2; ++mt) {
#pragma unroll
        for (int rh = 0; rh < 2; ++rh) {
            int r  = qt * 128 + w * 32 + mt * 16 + rh * 8 + g;
            int lq = n * WIN + r;
            float wgt = 1.0f;
            if (n != 0 && n != NW - 1) {
                if (r < FADE_)              wgt = (float)r * (1.0f / 63.0f);
                else if (r >= WIN - FADE_)  wgt = (float)(WIN - 1 - r) * (1.0f / 63.0f);
            }
            float sc = (wgt / (wgt + 1e-8f)) / lsum[mt * 2 + rh];
            float* dst = (float*)(Out + bho + (size_t)lq * D_);
#pragma unroll
            for (int nt = 0; nt < 8; ++nt) {
                float2 v;
                v.x = o[mt * 32 + nt * 4 + rh * 2 + 0] * sc;
                v.y = o[mt * 32 + nt * 4 + rh * 2 + 1] * sc;
                *(float2*)(dst + nt * 8 + tig * 2) = v;
            }
        }
    }
}

extern "C" void kernel_launch(void* const* d_in, const int* in_sizes, int n_in,
                              void* d_out, int out_size) {
    const float* Q   = (const float*)d_in[0];
    const float* K   = (const float*)d_in[1];
    const float* V   = (const float*)d_in[2];
    const void*  pos = (const void*)d_in[3];
    float* Out = (float*)d_out;

    cudaFuncSetAttribute(swa_mma_kernel,
                         cudaFuncAttributeMaxDynamicSharedMemorySize, SM_TOT);

    rope_table_kernel<<<(L_ * 32 + 255) / 256, 256>>>(pos);
    prep_kv_kernel<<<32 * NCHUNK, 128>>>(K, V);

    dim3 grid(NW * 4, H_, B_);
    swa_mma_kernel<<<grid, THREADS, SM_TOT>>>(Q, Out);
}